// round 1
// baseline (speedup 1.0000x reference)
#include <cuda_runtime.h>

#define F_DIM 513
#define T_DIM 256
#define C_DIM 8
#define N_DIM 4
#define TSPLIT 8
#define TCHUNK (T_DIM / TSPLIT)   // 32
#define TF (T_DIM * F_DIM)        // 131328
#define NF (N_DIM * F_DIM)        // 2052
#define DIAG_LOAD 7.0710678118654755e-4f  // 0.001/sqrt(2)

// Scratch: partial Hermitian covariances.
// Layout: [input(2: 0=target,1=noise)][n(4)][tchunk(8)][entry(64)][f(513)]
// entry 0..7 = diag (real), 8..35 = off-diag re (k-order), 36..63 = off-diag im
__device__ float g_partial[2 * N_DIM * TSPLIT * 64 * F_DIM];
// conj(W): [n][c][{re,im}][f]
__device__ float g_wc[N_DIM * C_DIM * 2 * F_DIM];

// -------------------------------------------------------------------------
// Pass 1: partial covariance accumulation (coalesced along f)
// grid: (ceil(F/128), TSPLIT, N*2)  block: 128
// -------------------------------------------------------------------------
__global__ __launch_bounds__(128) void cov_partial_kernel(
    const float* __restrict__ target, const float* __restrict__ noise)
{
    int f = blockIdx.x * blockDim.x + threadIdx.x;
    if (f >= F_DIM) return;
    int nz  = blockIdx.z;
    int inp = nz & 1;
    int n   = nz >> 1;
    const float* src = inp ? noise : target;
    int t0 = blockIdx.y * TCHUNK;

    float d[8], orr[28], oii[28];
#pragma unroll
    for (int i = 0; i < 8; i++) d[i] = 0.f;
#pragma unroll
    for (int i = 0; i < 28; i++) { orr[i] = 0.f; oii[i] = 0.f; }

    // layout (N, 2, C, T, F): idx = (((n*2+ri)*8+c)*T + t)*F + f
    const float* baseR = src + (size_t)(16 * n) * TF + f;
    const float* baseI = src + (size_t)(16 * n + 8) * TF + f;

    for (int t = t0; t < t0 + TCHUNK; ++t) {
        int off = t * F_DIM;
        float xr[8], xi[8];
#pragma unroll
        for (int c = 0; c < 8; c++) {
            xr[c] = __ldg(baseR + (size_t)c * TF + off);
            xi[c] = __ldg(baseI + (size_t)c * TF + off);
        }
#pragma unroll
        for (int i = 0; i < 8; i++)
            d[i] = fmaf(xr[i], xr[i], fmaf(xi[i], xi[i], d[i]));
        int k = 0;
#pragma unroll
        for (int i = 0; i < 8; i++)
#pragma unroll
            for (int j = i + 1; j < 8; j++) {
                // cov[i][j] = x_i * conj(x_j)
                orr[k] = fmaf(xr[i], xr[j], fmaf(xi[i], xi[j], orr[k]));
                oii[k] = fmaf(xi[i], xr[j], fmaf(-xr[i], xi[j], oii[k]));
                k++;
            }
    }

    float* dst = g_partial +
        ((size_t)((inp * N_DIM + n) * TSPLIT + blockIdx.y) * 64) * F_DIM + f;
#pragma unroll
    for (int i = 0; i < 8; i++) dst[(size_t)i * F_DIM] = d[i];
#pragma unroll
    for (int k2 = 0; k2 < 28; k2++) {
        dst[(size_t)(8 + k2) * F_DIM]  = orr[k2];
        dst[(size_t)(36 + k2) * F_DIM] = oii[k2];
    }
}

// -------------------------------------------------------------------------
// Pass 2: per-(n,f) reduce + diagonal load + 8x8 complex Gauss-Jordan
// inverse (8 lanes per matrix, width-8 shuffles) + trace + W.
// grid: ceil(2052/32) blocks of 256 threads (32 matrices/block)
// -------------------------------------------------------------------------
__device__ __forceinline__ void load_row(
    int ip, int n, int f, int i, float invT, float* rr, float* ri)
{
    const float* base =
        g_partial + (size_t)(ip * N_DIM + n) * TSPLIT * 64 * F_DIM + f;
    const size_t cs = (size_t)64 * F_DIM;  // chunk stride
#pragma unroll
    for (int j = 0; j < 8; j++) {
        bool diag = (j == i);
        int a = min(i, j), b = max(i, j);
        int k = 7 * a - (a * (a - 1)) / 2 + (b - a - 1);  // k==-1 when diag
        int e_re = diag ? i : (8 + k);
        int e_im = diag ? 35 : (36 + k);  // in-bounds dummy for diag
        float sre = 0.f, sim = 0.f;
#pragma unroll
        for (int ch = 0; ch < TSPLIT; ch++) {
            sre += base[ch * cs + (size_t)e_re * F_DIM];
            sim += base[ch * cs + (size_t)e_im * F_DIM];
        }
        float sign = (i < j) ? 1.f : -1.f;
        rr[j] = sre * invT;
        ri[j] = diag ? 0.f : sign * sim * invT;
    }
}

__global__ __launch_bounds__(256) void solve_kernel(const int* __restrict__ ref_idx)
{
    int gid  = blockIdx.x * (blockDim.x >> 3) + (threadIdx.x >> 3);
    int lane = threadIdx.x & 7;
    int m = gid;
    if (m >= NF) m = NF - 1;  // duplicate work (idempotent), keeps warp converged
    int n = m / F_DIM, f = m % F_DIM;
    int i = lane;
    const float invT = 1.0f / (float)T_DIM;
    const unsigned FULL = 0xffffffffu;

    // Noise covariance row i (will be overwritten by inv(Pn) row i)
    float nr[8], ni[8];
    load_row(1, n, f, i, invT, nr, ni);
    nr[i] += DIAG_LOAD;
    ni[i] += DIAG_LOAD;

    // In-place Gauss-Jordan inversion, rows distributed across 8 lanes.
#pragma unroll
    for (int k = 0; k < 8; k++) {
        float akk_r = __shfl_sync(FULL, nr[k], k, 8);
        float akk_i = __shfl_sync(FULL, ni[k], k, 8);
        float idn = 1.0f / fmaf(akk_r, akk_r, akk_i * akk_i);
        float p_r = akk_r * idn, p_i = -akk_i * idn;
        float s_r[8], s_i[8];
#pragma unroll
        for (int j = 0; j < 8; j++) {
            float ar = __shfl_sync(FULL, nr[j], k, 8);
            float ai = __shfl_sync(FULL, ni[j], k, 8);
            s_r[j] = ar * p_r - ai * p_i;
            s_i[j] = ar * p_i + ai * p_r;
        }
        if (i == k) {
#pragma unroll
            for (int j = 0; j < 8; j++) { nr[j] = s_r[j]; ni[j] = s_i[j]; }
            nr[k] = p_r; ni[k] = p_i;
        } else {
            float f_r = nr[k], f_i = ni[k];
#pragma unroll
            for (int j = 0; j < 8; j++) {
                if (j == k) continue;
                nr[j] -= f_r * s_r[j] - f_i * s_i[j];
                ni[j] -= f_r * s_i[j] + f_i * s_r[j];
            }
            nr[k] = -(f_r * p_r - f_i * p_i);
            ni[k] = -(f_r * p_i + f_i * p_r);
        }
    }

    // Target covariance row i
    float tr_[8], ti[8];
    load_row(0, n, f, i, invT, tr_, ti);

    // trace(inv(Pn) @ Pt): lane i computes sum_j inv[i][j] * Pt[j][i],
    // Pt[j][i] = conj(Pt[i][j]) (Pt Hermitian by construction).
    float trc_r = 0.f, trc_i = 0.f;
#pragma unroll
    for (int j = 0; j < 8; j++) {
        trc_r += nr[j] * tr_[j] + ni[j] * ti[j];
        trc_i += ni[j] * tr_[j] - nr[j] * ti[j];
    }
#pragma unroll
    for (int off = 4; off > 0; off >>= 1) {
        trc_r += __shfl_xor_sync(FULL, trc_r, off, 8);
        trc_i += __shfl_xor_sync(FULL, trc_i, off, 8);
    }

    // Pt[:, ref] column: lane j contributes Pt[j][ref]
    int ref = *ref_idx;
    float pr = 0.f, pi = 0.f;
#pragma unroll
    for (int jj = 0; jj < 8; jj++)
        if (jj == ref) { pr = tr_[jj]; pi = ti[jj]; }

    float w_r = 0.f, w_i = 0.f;
#pragma unroll
    for (int j = 0; j < 8; j++) {
        float br = __shfl_sync(FULL, pr, j, 8);
        float bi = __shfl_sync(FULL, pi, j, 8);
        w_r += nr[j] * br - ni[j] * bi;
        w_i += nr[j] * bi + ni[j] * br;
    }

    // W = w / trace (complex division)
    float ldn = 1.0f / fmaf(trc_r, trc_r, trc_i * trc_i);
    float lr = trc_r * ldn, li = -trc_i * ldn;
    float Wr = w_r * lr - w_i * li;
    float Wi = w_r * li + w_i * lr;

    // store conj(W) for the beamform pass
    g_wc[((n * 8 + i) * 2 + 0) * F_DIM + f] = Wr;
    g_wc[((n * 8 + i) * 2 + 1) * F_DIM + f] = -Wi;
}

// -------------------------------------------------------------------------
// Pass 3: beamform X[n,t,f] = sum_c conj(W)[n,f,c] * y[n,c,t,f]
// grid: (ceil(F/128), T/4, N)  block: 128, 4 t's per thread
// -------------------------------------------------------------------------
#define TPER 4
__global__ __launch_bounds__(128) void beamform_kernel(
    const float* __restrict__ mix, float* __restrict__ out)
{
    int f = blockIdx.x * blockDim.x + threadIdx.x;
    if (f >= F_DIM) return;
    int n  = blockIdx.z;
    int t0 = blockIdx.y * TPER;

    float wr[8], wi[8];
#pragma unroll
    for (int c = 0; c < 8; c++) {
        wr[c] = g_wc[((n * 8 + c) * 2 + 0) * F_DIM + f];
        wi[c] = g_wc[((n * 8 + c) * 2 + 1) * F_DIM + f];
    }

    const float* baseR = mix + (size_t)(16 * n) * TF + f;
    const float* baseI = mix + (size_t)(16 * n + 8) * TF + f;
    float* outR = out + (size_t)(2 * n) * TF + f;      // (N,2,1,T,F)
    float* outI = out + (size_t)(2 * n + 1) * TF + f;

#pragma unroll
    for (int dt = 0; dt < TPER; dt++) {
        int off = (t0 + dt) * F_DIM;
        float Xr = 0.f, Xi = 0.f;
#pragma unroll
        for (int c = 0; c < 8; c++) {
            float yr = __ldg(baseR + (size_t)c * TF + off);
            float yi = __ldg(baseI + (size_t)c * TF + off);
            Xr += wr[c] * yr - wi[c] * yi;   // a=conj(W): Xr = ar*yr - ai*yi
            Xi += wr[c] * yi + wi[c] * yr;   //            Xi = ar*yi + ai*yr
        }
        outR[off] = Xr;
        outI[off] = Xi;
    }
}

// -------------------------------------------------------------------------
extern "C" void kernel_launch(void* const* d_in, const int* in_sizes, int n_in,
                              void* d_out, int out_size)
{
    const float* mixture = (const float*)d_in[0];
    const float* target  = (const float*)d_in[1];
    const float* noise   = (const float*)d_in[2];
    const int*   ref     = (const int*)d_in[3];
    float* out = (float*)d_out;

    dim3 g1((F_DIM + 127) / 128, TSPLIT, N_DIM * 2);
    cov_partial_kernel<<<g1, 128>>>(target, noise);

    int groups = (NF + 31) / 32;  // 32 matrices per 256-thread block
    solve_kernel<<<groups, 256>>>(ref);

    dim3 g3((F_DIM + 127) / 128, T_DIM / TPER, N_DIM);
    beamform_kernel<<<g3, 128>>>(mixture, out);
}

// round 2
// speedup vs baseline: 1.0427x; 1.0427x over previous
#include <cuda_runtime.h>

#define F_DIM 513
#define T_DIM 256
#define C_DIM 8
#define N_DIM 4
#define TSPLIT 8
#define TCHUNK (T_DIM / TSPLIT)   // 32
#define TF (T_DIM * F_DIM)        // 131328
#define NF (N_DIM * F_DIM)        // 2052
#define DIAG_LOAD 7.0710678118654755e-4f  // 0.001/sqrt(2)

// Scratch: partial Hermitian covariances.
// Layout: [input(2)][n(4)][tchunk(8)][entry(64)][f(513)]
// entry 0..7 = diag (real), 8..35 = off-diag re, 36..63 = off-diag im
__device__ float g_partial[2 * N_DIM * TSPLIT * 64 * F_DIM];
// conj(W): [n][c][{re,im}][f]
__device__ float g_wc[N_DIM * C_DIM * 2 * F_DIM];

// -------------------------------------------------------------------------
// Pass 1: partial covariance. Block = (128 f, 2 t-subthreads) = 256 thr.
// Each thread accumulates 16 t's into 64 regs, then a deterministic smem
// reduction over the 2 subthreads, coalesced STG of the 64 entries.
// grid: (5, TSPLIT, N*2)
// -------------------------------------------------------------------------
__global__ __launch_bounds__(256, 2) void cov_partial_kernel(
    const float* __restrict__ target, const float* __restrict__ noise)
{
    int fLocal = threadIdx.x;                 // 0..127
    int k      = threadIdx.y;                 // 0..1
    int f  = blockIdx.x * 128 + fLocal;
    int fc = min(f, F_DIM - 1);               // clamp; dup work, no store
    int nz  = blockIdx.z;
    int inp = nz & 1;
    int n   = nz >> 1;
    const float* src = inp ? noise : target;
    int t0 = blockIdx.y * TCHUNK + k * (TCHUNK / 2);

    float acc[64];
#pragma unroll
    for (int i = 0; i < 64; i++) acc[i] = 0.f;

    // layout (N, 2, C, T, F): idx = (((n*2+ri)*8+c)*T + t)*F + f
    const float* baseR = src + (size_t)(16 * n) * TF + fc;
    const float* baseI = src + (size_t)(16 * n + 8) * TF + fc;

    for (int t = t0; t < t0 + TCHUNK / 2; ++t) {
        int off = t * F_DIM;
        float xr[8], xi[8];
#pragma unroll
        for (int c = 0; c < 8; c++) {
            xr[c] = __ldg(baseR + (size_t)c * TF + off);
            xi[c] = __ldg(baseI + (size_t)c * TF + off);
        }
#pragma unroll
        for (int i = 0; i < 8; i++)
            acc[i] = fmaf(xr[i], xr[i], fmaf(xi[i], xi[i], acc[i]));
        int kk = 0;
#pragma unroll
        for (int i = 0; i < 8; i++)
#pragma unroll
            for (int j = i + 1; j < 8; j++) {
                acc[8 + kk]  = fmaf(xr[i], xr[j], fmaf(xi[i], xi[j], acc[8 + kk]));
                acc[36 + kk] = fmaf(xi[i], xr[j], fmaf(-xr[i], xi[j], acc[36 + kk]));
                kk++;
            }
    }

    // Cross-subthread reduction: 8 chunks of 8 entries via smem.
    __shared__ float s[2][128][9];  // pad 9 to dodge bank conflicts
    float* dstBase = g_partial +
        (size_t)((inp * N_DIM + n) * TSPLIT + blockIdx.y) * 64 * F_DIM;
    int tid = k * 128 + fLocal;

#pragma unroll
    for (int c = 0; c < 8; c++) {
#pragma unroll
        for (int e = 0; e < 8; e++) s[k][fLocal][e] = acc[c * 8 + e];
        __syncthreads();
#pragma unroll
        for (int r = 0; r < 4; r++) {
            int o   = r * 256 + tid;      // 0..1023 = 8 entries x 128 f
            int e_o = o >> 7;
            int f_o = o & 127;
            float v = s[0][f_o][e_o] + s[1][f_o][e_o];
            int gf = blockIdx.x * 128 + f_o;
            if (gf < F_DIM)
                dstBase[(size_t)(c * 8 + e_o) * F_DIM + gf] = v;
        }
        __syncthreads();
    }
}

// -------------------------------------------------------------------------
// Pass 2: per-(n,f) solve. Block = 256 thr = 32 matrices.
// Stage 1: coalesced cooperative load of all covariance entries (+chunk
// reduction) into smem. Stage 2: 8-lane complex Gauss-Jordan per matrix.
// -------------------------------------------------------------------------
__global__ __launch_bounds__(256) void solve_kernel(const int* __restrict__ ref_idx)
{
    __shared__ float s_cov[2][64][33];   // [input][entry][matrix + pad]
    int tid = threadIdx.x;
    int m0  = blockIdx.x * 32;
    const float invT = 1.0f / (float)T_DIM;

    // Cooperative staged load: 2*64*32 = 4096 outputs, 16 per thread.
    // Lanes vary mi fastest -> consecutive f -> coalesced LDG.
#pragma unroll
    for (int r = 0; r < 16; r++) {
        int o  = r * 256 + tid;
        int mi = o & 31;
        int e  = (o >> 5) & 63;
        int ip = o >> 11;
        int m  = min(m0 + mi, NF - 1);
        int n  = m / F_DIM, f = m % F_DIM;
        const float* base = g_partial +
            (size_t)((ip * N_DIM + n) * TSPLIT) * 64 * F_DIM +
            (size_t)e * F_DIM + f;
        float sv = 0.f;
#pragma unroll
        for (int ch = 0; ch < TSPLIT; ch++)
            sv += base[(size_t)ch * 64 * F_DIM];
        s_cov[ip][e][mi] = sv * invT;
    }
    __syncthreads();

    int mi = tid >> 3;
    int i  = tid & 7;
    int m  = min(m0 + mi, NF - 1);
    int n  = m / F_DIM, f = m % F_DIM;
    const unsigned FULL = 0xffffffffu;

    // Noise covariance row i from smem (+ diagonal load)
    float nr[8], ni[8];
#pragma unroll
    for (int j = 0; j < 8; j++) {
        if (j == i) { nr[j] = s_cov[1][i][mi] + DIAG_LOAD; ni[j] = DIAG_LOAD; }
        else {
            int a = min(i, j), b = max(i, j);
            int kk = 7 * a - (a * (a - 1)) / 2 + (b - a - 1);
            float sign = (i < j) ? 1.f : -1.f;
            nr[j] = s_cov[1][8 + kk][mi];
            ni[j] = sign * s_cov[1][36 + kk][mi];
        }
    }

    // In-place complex Gauss-Jordan, rows across 8 lanes.
#pragma unroll
    for (int kp = 0; kp < 8; kp++) {
        float akk_r = __shfl_sync(FULL, nr[kp], kp, 8);
        float akk_i = __shfl_sync(FULL, ni[kp], kp, 8);
        float idn = 1.0f / fmaf(akk_r, akk_r, akk_i * akk_i);
        float p_r = akk_r * idn, p_i = -akk_i * idn;
        float s_r[8], s_i[8];
#pragma unroll
        for (int j = 0; j < 8; j++) {
            float ar = __shfl_sync(FULL, nr[j], kp, 8);
            float ai = __shfl_sync(FULL, ni[j], kp, 8);
            s_r[j] = ar * p_r - ai * p_i;
            s_i[j] = ar * p_i + ai * p_r;
        }
        if (i == kp) {
#pragma unroll
            for (int j = 0; j < 8; j++) { nr[j] = s_r[j]; ni[j] = s_i[j]; }
            nr[kp] = p_r; ni[kp] = p_i;
        } else {
            float f_r = nr[kp], f_i = ni[kp];
#pragma unroll
            for (int j = 0; j < 8; j++) {
                if (j == kp) continue;
                nr[j] -= f_r * s_r[j] - f_i * s_i[j];
                ni[j] -= f_r * s_i[j] + f_i * s_r[j];
            }
            nr[kp] = -(f_r * p_r - f_i * p_i);
            ni[kp] = -(f_r * p_i + f_i * p_r);
        }
    }

    // Target covariance row i from smem
    float tr_[8], ti[8];
#pragma unroll
    for (int j = 0; j < 8; j++) {
        if (j == i) { tr_[j] = s_cov[0][i][mi]; ti[j] = 0.f; }
        else {
            int a = min(i, j), b = max(i, j);
            int kk = 7 * a - (a * (a - 1)) / 2 + (b - a - 1);
            float sign = (i < j) ? 1.f : -1.f;
            tr_[j] = s_cov[0][8 + kk][mi];
            ti[j]  = sign * s_cov[0][36 + kk][mi];
        }
    }

    // trace(inv(Pn) @ Pt): lane i holds sum_j inv[i][j]*conj(Pt[i][j])
    float trc_r = 0.f, trc_i = 0.f;
#pragma unroll
    for (int j = 0; j < 8; j++) {
        trc_r += nr[j] * tr_[j] + ni[j] * ti[j];
        trc_i += ni[j] * tr_[j] - nr[j] * ti[j];
    }
#pragma unroll
    for (int off = 4; off > 0; off >>= 1) {
        trc_r += __shfl_xor_sync(FULL, trc_r, off, 8);
        trc_i += __shfl_xor_sync(FULL, trc_i, off, 8);
    }

    // Pt[:, ref] column: lane j contributes Pt[j][ref]
    int ref = *ref_idx;
    float pr = 0.f, pi = 0.f;
#pragma unroll
    for (int jj = 0; jj < 8; jj++)
        if (jj == ref) { pr = tr_[jj]; pi = ti[jj]; }

    float w_r = 0.f, w_i = 0.f;
#pragma unroll
    for (int j = 0; j < 8; j++) {
        float br = __shfl_sync(FULL, pr, j, 8);
        float bi = __shfl_sync(FULL, pi, j, 8);
        w_r += nr[j] * br - ni[j] * bi;
        w_i += nr[j] * bi + ni[j] * br;
    }

    // W = w / trace
    float ldn = 1.0f / fmaf(trc_r, trc_r, trc_i * trc_i);
    float lr = trc_r * ldn, li = -trc_i * ldn;
    float Wr = w_r * lr - w_i * li;
    float Wi = w_r * li + w_i * lr;

    g_wc[((n * 8 + i) * 2 + 0) * F_DIM + f] = Wr;
    g_wc[((n * 8 + i) * 2 + 1) * F_DIM + f] = -Wi;
}

// -------------------------------------------------------------------------
// Pass 3: beamform X[n,t,f] = sum_c conj(W)[n,f,c] * y[n,c,t,f]
// grid: (5, T/4, N)  block: 128, 4 t's per thread
// -------------------------------------------------------------------------
#define TPER 4
__global__ __launch_bounds__(128) void beamform_kernel(
    const float* __restrict__ mix, float* __restrict__ out)
{
    int f = blockIdx.x * blockDim.x + threadIdx.x;
    if (f >= F_DIM) return;
    int n  = blockIdx.z;
    int t0 = blockIdx.y * TPER;

    float wr[8], wi[8];
#pragma unroll
    for (int c = 0; c < 8; c++) {
        wr[c] = g_wc[((n * 8 + c) * 2 + 0) * F_DIM + f];
        wi[c] = g_wc[((n * 8 + c) * 2 + 1) * F_DIM + f];
    }

    const float* baseR = mix + (size_t)(16 * n) * TF + f;
    const float* baseI = mix + (size_t)(16 * n + 8) * TF + f;
    float* outR = out + (size_t)(2 * n) * TF + f;      // (N,2,1,T,F)
    float* outI = out + (size_t)(2 * n + 1) * TF + f;

#pragma unroll
    for (int dt = 0; dt < TPER; dt++) {
        int off = (t0 + dt) * F_DIM;
        float Xr = 0.f, Xi = 0.f;
#pragma unroll
        for (int c = 0; c < 8; c++) {
            float yr = __ldg(baseR + (size_t)c * TF + off);
            float yi = __ldg(baseI + (size_t)c * TF + off);
            Xr += wr[c] * yr - wi[c] * yi;
            Xi += wr[c] * yi + wi[c] * yr;
        }
        outR[off] = Xr;
        outI[off] = Xi;
    }
}

// -------------------------------------------------------------------------
extern "C" void kernel_launch(void* const* d_in, const int* in_sizes, int n_in,
                              void* d_out, int out_size)
{
    const float* mixture = (const float*)d_in[0];
    const float* target  = (const float*)d_in[1];
    const float* noise   = (const float*)d_in[2];
    const int*   ref     = (const int*)d_in[3];
    float* out = (float*)d_out;

    dim3 b1(128, 2);
    dim3 g1((F_DIM + 127) / 128, TSPLIT, N_DIM * 2);
    cov_partial_kernel<<<g1, b1>>>(target, noise);

    int groups = (NF + 31) / 32;
    solve_kernel<<<groups, 256>>>(ref);

    dim3 g3((F_DIM + 127) / 128, T_DIM / TPER, N_DIM);
    beamform_kernel<<<g3, 128>>>(mixture, out);
}

// round 3
// speedup vs baseline: 1.3536x; 1.2981x over previous
#include <cuda_runtime.h>

#define F_DIM 513
#define T_DIM 256
#define C_DIM 8
#define N_DIM 4
#define TSPLIT 7
#define TF (T_DIM * F_DIM)        // 131328
#define NF (N_DIM * F_DIM)        // 2052
#define DIAG_LOAD 7.0710678118654755e-4f  // 0.001/sqrt(2)

// Partial Hermitian covariances: [input(2)][n(4)][chunk(7)][entry(64)][f(513)]
// entry 0..7 = diag (real), 8..35 = off-diag re (kk order), 36..63 = off-diag im
__device__ float g_partial[2 * N_DIM * TSPLIT * 64 * F_DIM];
// conj(W): [n][c][{re,im}][f]
__device__ float g_wc[N_DIM * C_DIM * 2 * F_DIM];

// t-chunk boundaries for TSPLIT=7: sizes 37,37,37,37,36,36,36
__device__ __forceinline__ int chunk_start(int y) { return y * 36 + min(y, 4); }

// local accumulator index -> global entry index
__device__ __forceinline__ int gmap(int h, int l) {
    // h0: l<8 diag(l); 8..19 -> orr kk=l-8 (8..19); 20..31 -> oii kk=l-20 (36..47)
    // h1: l<16 -> orr kk=12+l (20..35); 16..31 -> oii kk=12+(l-16) (48..63)
    return h == 0 ? (l < 20 ? l : l + 16) : (l < 16 ? 20 + l : 32 + l);
}

// -------------------------------------------------------------------------
// Pass 1: partial covariance.
// Block (128 f, 4): threadIdx.y = h*2+k, h = entry-half, k = t-subchunk.
// 32 accumulators/thread, <=64 regs, 2 blocks/SM -> 50% occupancy.
// grid: (5, 7, 8) = 280 blocks (single wave at 2 blocks/SM on 148 SMs).
// -------------------------------------------------------------------------
__global__ __launch_bounds__(512, 2) void cov_partial_kernel(
    const float* __restrict__ target, const float* __restrict__ noise)
{
    int fLocal = threadIdx.x;          // 0..127
    int h = threadIdx.y >> 1;          // entry half
    int k = threadIdx.y & 1;           // t sub
    int f  = blockIdx.x * 128 + fLocal;
    int fc = min(f, F_DIM - 1);
    int inp = blockIdx.z & 1;
    int n   = blockIdx.z >> 1;
    const float* src = inp ? noise : target;

    int cs = chunk_start(blockIdx.y);
    int ce = chunk_start(blockIdx.y + 1);
    int half = (ce - cs + 1) >> 1;
    int t0 = cs + k * half;
    int t1 = k ? ce : cs + half;

    float acc[32];
#pragma unroll
    for (int i = 0; i < 32; i++) acc[i] = 0.f;

    // layout (N, 2, C, T, F)
    const float* baseR = src + (size_t)(16 * n) * TF + fc;
    const float* baseI = src + (size_t)(16 * n + 8) * TF + fc;

    if (h == 0) {
        // diag 0..7 + pairs kk=0..11: i=0 (j=1..7), i=1 (j=2..6)
#pragma unroll 4
        for (int t = t0; t < t1; ++t) {
            int off = t * F_DIM;
            float xr[8], xi[8];
#pragma unroll
            for (int c = 0; c < 8; c++) {
                xr[c] = __ldg(baseR + (size_t)c * TF + off);
                xi[c] = __ldg(baseI + (size_t)c * TF + off);
            }
#pragma unroll
            for (int i = 0; i < 8; i++)
                acc[i] = fmaf(xr[i], xr[i], fmaf(xi[i], xi[i], acc[i]));
            int kk = 0;
#pragma unroll
            for (int i = 0; i < 2; i++)
#pragma unroll
                for (int j = i + 1; j < 8; j++) {
                    if (kk < 12) {
                        acc[8 + kk]  = fmaf(xr[i], xr[j], fmaf(xi[i], xi[j], acc[8 + kk]));
                        acc[20 + kk] = fmaf(xi[i], xr[j], fmaf(-xr[i], xi[j], acc[20 + kk]));
                    }
                    kk++;
                }
        }
    } else {
        // pairs kk=12..27: (1,7), i=2..6 all j
#pragma unroll 4
        for (int t = t0; t < t1; ++t) {
            int off = t * F_DIM;
            float xr[8], xi[8];
#pragma unroll
            for (int c = 1; c < 8; c++) {   // channel 0 unused by half 1
                xr[c] = __ldg(baseR + (size_t)c * TF + off);
                xi[c] = __ldg(baseI + (size_t)c * TF + off);
            }
            int kk = 0;   // local kk = global kk - 12
#pragma unroll
            for (int i = 1; i < 8; i++)
#pragma unroll
                for (int j = i + 1; j < 8; j++) {
                    int gkk = 7 * i - (i * (i - 1)) / 2 + (j - i - 1);
                    if (gkk >= 12) {
                        kk = gkk - 12;
                        acc[kk]      = fmaf(xr[i], xr[j], fmaf(xi[i], xi[j], acc[kk]));
                        acc[16 + kk] = fmaf(xi[i], xr[j], fmaf(-xr[i], xi[j], acc[16 + kk]));
                    }
                }
        }
    }

    // Reduce over k (2 subchunks) via smem; coalesced global store.
    __shared__ float s[2][2][128][9];   // [h][k][f][entry-in-batch pad 9]
    float* dstBase = g_partial +
        (size_t)((inp * N_DIM + n) * TSPLIT + blockIdx.y) * 64 * F_DIM;

#pragma unroll
    for (int b = 0; b < 4; b++) {
#pragma unroll
        for (int e = 0; e < 8; e++) s[h][k][fLocal][e] = acc[b * 8 + e];
        __syncthreads();
        // 8 entries x 128 f per half = 1024 outputs; 256 threads per half, 4 each
#pragma unroll
        for (int r = 0; r < 4; r++) {
            int o   = r * 256 + k * 128 + fLocal;
            int e_o = o >> 7;
            int f_o = o & 127;
            float v = s[h][0][f_o][e_o] + s[h][1][f_o][e_o];
            int gf = blockIdx.x * 128 + f_o;
            if (gf < F_DIM)
                dstBase[(size_t)gmap(h, b * 8 + e_o) * F_DIM + gf] = v;
        }
        __syncthreads();
    }
}

// -------------------------------------------------------------------------
// Pass 2: per-(n,f) solve. Block = 256 thr = 32 matrices.
// -------------------------------------------------------------------------
__global__ __launch_bounds__(256) void solve_kernel(const int* __restrict__ ref_idx)
{
    __shared__ float s_cov[2][64][33];   // [input][entry][matrix + pad]
    int tid = threadIdx.x;
    int m0  = blockIdx.x * 32;
    const float invT = 1.0f / (float)T_DIM;

    // Cooperative staged load: 2*64*32 = 4096 outputs, 16 per thread.
#pragma unroll
    for (int r = 0; r < 16; r++) {
        int o  = r * 256 + tid;
        int mi = o & 31;
        int e  = (o >> 5) & 63;
        int ip = o >> 11;
        int m  = min(m0 + mi, NF - 1);
        int n  = m / F_DIM, f = m % F_DIM;
        const float* base = g_partial +
            (size_t)((ip * N_DIM + n) * TSPLIT) * 64 * F_DIM +
            (size_t)e * F_DIM + f;
        float sv = 0.f;
#pragma unroll
        for (int ch = 0; ch < TSPLIT; ch++)
            sv += base[(size_t)ch * 64 * F_DIM];
        s_cov[ip][e][mi] = sv * invT;
    }
    __syncthreads();

    int mi = tid >> 3;
    int i  = tid & 7;
    int m  = min(m0 + mi, NF - 1);
    int n  = m / F_DIM, f = m % F_DIM;
    const unsigned FULL = 0xffffffffu;

    // Noise covariance row i (+ diagonal load)
    float nr[8], ni[8];
#pragma unroll
    for (int j = 0; j < 8; j++) {
        if (j == i) { nr[j] = s_cov[1][i][mi] + DIAG_LOAD; ni[j] = DIAG_LOAD; }
        else {
            int a = min(i, j), b = max(i, j);
            int kk = 7 * a - (a * (a - 1)) / 2 + (b - a - 1);
            float sign = (i < j) ? 1.f : -1.f;
            nr[j] = s_cov[1][8 + kk][mi];
            ni[j] = sign * s_cov[1][36 + kk][mi];
        }
    }

    // In-place complex Gauss-Jordan, rows across 8 lanes.
#pragma unroll
    for (int kp = 0; kp < 8; kp++) {
        float akk_r = __shfl_sync(FULL, nr[kp], kp, 8);
        float akk_i = __shfl_sync(FULL, ni[kp], kp, 8);
        float idn = 1.0f / fmaf(akk_r, akk_r, akk_i * akk_i);
        float p_r = akk_r * idn, p_i = -akk_i * idn;
        float s_r[8], s_i[8];
#pragma unroll
        for (int j = 0; j < 8; j++) {
            float ar = __shfl_sync(FULL, nr[j], kp, 8);
            float ai = __shfl_sync(FULL, ni[j], kp, 8);
            s_r[j] = ar * p_r - ai * p_i;
            s_i[j] = ar * p_i + ai * p_r;
        }
        if (i == kp) {
#pragma unroll
            for (int j = 0; j < 8; j++) { nr[j] = s_r[j]; ni[j] = s_i[j]; }
            nr[kp] = p_r; ni[kp] = p_i;
        } else {
            float f_r = nr[kp], f_i = ni[kp];
#pragma unroll
            for (int j = 0; j < 8; j++) {
                if (j == kp) continue;
                nr[j] -= f_r * s_r[j] - f_i * s_i[j];
                ni[j] -= f_r * s_i[j] + f_i * s_r[j];
            }
            nr[kp] = -(f_r * p_r - f_i * p_i);
            ni[kp] = -(f_r * p_i + f_i * p_r);
        }
    }

    // Target covariance row i
    float tr_[8], ti[8];
#pragma unroll
    for (int j = 0; j < 8; j++) {
        if (j == i) { tr_[j] = s_cov[0][i][mi]; ti[j] = 0.f; }
        else {
            int a = min(i, j), b = max(i, j);
            int kk = 7 * a - (a * (a - 1)) / 2 + (b - a - 1);
            float sign = (i < j) ? 1.f : -1.f;
            tr_[j] = s_cov[0][8 + kk][mi];
            ti[j]  = sign * s_cov[0][36 + kk][mi];
        }
    }

    // trace(inv(Pn) @ Pt)
    float trc_r = 0.f, trc_i = 0.f;
#pragma unroll
    for (int j = 0; j < 8; j++) {
        trc_r += nr[j] * tr_[j] + ni[j] * ti[j];
        trc_i += ni[j] * tr_[j] - nr[j] * ti[j];
    }
#pragma unroll
    for (int off = 4; off > 0; off >>= 1) {
        trc_r += __shfl_xor_sync(FULL, trc_r, off, 8);
        trc_i += __shfl_xor_sync(FULL, trc_i, off, 8);
    }

    // Pt[:, ref]
    int ref = *ref_idx;
    float pr = 0.f, pi = 0.f;
#pragma unroll
    for (int jj = 0; jj < 8; jj++)
        if (jj == ref) { pr = tr_[jj]; pi = ti[jj]; }

    float w_r = 0.f, w_i = 0.f;
#pragma unroll
    for (int j = 0; j < 8; j++) {
        float br = __shfl_sync(FULL, pr, j, 8);
        float bi = __shfl_sync(FULL, pi, j, 8);
        w_r += nr[j] * br - ni[j] * bi;
        w_i += nr[j] * bi + ni[j] * br;
    }

    float ldn = 1.0f / fmaf(trc_r, trc_r, trc_i * trc_i);
    float lr = trc_r * ldn, li = -trc_i * ldn;
    float Wr = w_r * lr - w_i * li;
    float Wi = w_r * li + w_i * lr;

    g_wc[((n * 8 + i) * 2 + 0) * F_DIM + f] = Wr;
    g_wc[((n * 8 + i) * 2 + 1) * F_DIM + f] = -Wi;
}

// -------------------------------------------------------------------------
// Pass 3: beamform. TPER=2, grid (5, 128, 4) = 2560 blocks for occupancy.
// -------------------------------------------------------------------------
#define TPER 2
__global__ __launch_bounds__(128) void beamform_kernel(
    const float* __restrict__ mix, float* __restrict__ out)
{
    int f = blockIdx.x * blockDim.x + threadIdx.x;
    if (f >= F_DIM) return;
    int n  = blockIdx.z;
    int t0 = blockIdx.y * TPER;

    float wr[8], wi[8];
#pragma unroll
    for (int c = 0; c < 8; c++) {
        wr[c] = g_wc[((n * 8 + c) * 2 + 0) * F_DIM + f];
        wi[c] = g_wc[((n * 8 + c) * 2 + 1) * F_DIM + f];
    }

    const float* baseR = mix + (size_t)(16 * n) * TF + f;
    const float* baseI = mix + (size_t)(16 * n + 8) * TF + f;
    float* outR = out + (size_t)(2 * n) * TF + f;      // (N,2,1,T,F)
    float* outI = out + (size_t)(2 * n + 1) * TF + f;

#pragma unroll
    for (int dt = 0; dt < TPER; dt++) {
        int off = (t0 + dt) * F_DIM;
        float Xr = 0.f, Xi = 0.f;
#pragma unroll
        for (int c = 0; c < 8; c++) {
            float yr = __ldg(baseR + (size_t)c * TF + off);
            float yi = __ldg(baseI + (size_t)c * TF + off);
            Xr += wr[c] * yr - wi[c] * yi;
            Xi += wr[c] * yi + wi[c] * yr;
        }
        outR[off] = Xr;
        outI[off] = Xi;
    }
}

// -------------------------------------------------------------------------
extern "C" void kernel_launch(void* const* d_in, const int* in_sizes, int n_in,
                              void* d_out, int out_size)
{
    const float* mixture = (const float*)d_in[0];
    const float* target  = (const float*)d_in[1];
    const float* noise   = (const float*)d_in[2];
    const int*   ref     = (const int*)d_in[3];
    float* out = (float*)d_out;

    dim3 b1(128, 4);
    dim3 g1((F_DIM + 127) / 128, TSPLIT, N_DIM * 2);   // 5 x 7 x 8 = 280 blocks
    cov_partial_kernel<<<g1, b1>>>(target, noise);

    int groups = (NF + 31) / 32;
    solve_kernel<<<groups, 256>>>(ref);

    dim3 g3((F_DIM + 127) / 128, T_DIM / TPER, N_DIM);
    beamform_kernel<<<g3, 128>>>(mixture, out);
}